// round 5
// baseline (speedup 1.0000x reference)
#include <cuda_runtime.h>
#include <cuda_bf16.h>
#include <cstdint>
#include <math.h>

#define DINLINE static __device__ __forceinline__

// Arch-feature detection: tcgen05 requires an 'a' (arch-specific) or 'f'
// (family-specific) compilation target. On plain sm_103 ptxas rejects it.
#if defined(__CUDA_ARCH_FEAT_SM103_ALL) || defined(__CUDA_ARCH_FEAT_SM100_ALL) || \
    defined(__CUDA_ARCH_SPECIFIC__) || defined(__CUDA_ARCH_FAMILY_SPECIFIC__)
#define HAS_TCGEN05 1
#else
#define HAS_TCGEN05 0
#endif

// ---------------- problem dims ----------------
#define BATCH   16384
#define NCONT   13
#define EMB     128
#define NTAB    26
#define VOCAB   100000
#define K1      3456      // EMB*(1+NTAB)
#define N1      1024
#define N2      512
#define N3      256

// ---------------- scratch (device globals; no allocs allowed) ----------------
__device__ __nv_bfloat16 g_H0[(size_t)BATCH * K1];
__device__ __nv_bfloat16 g_H1[(size_t)BATCH * N1];
__device__ __nv_bfloat16 g_H2[(size_t)BATCH * N2];
__device__ __nv_bfloat16 g_H3[(size_t)BATCH * N3];
__device__ __nv_bfloat16 g_W1T[(size_t)N1 * K1];
__device__ __nv_bfloat16 g_W2T[(size_t)N2 * N1];
__device__ __nv_bfloat16 g_W3T[(size_t)N3 * N2];
__device__ int g_is64;

// ---------------- baseline PTX helpers ----------------
DINLINE uint32_t smem_u32(const void* p) {
    uint32_t a;
    asm("{ .reg .u64 t; cvta.to.shared.u64 t, %1; cvt.u32.u64 %0, t; }" : "=r"(a) : "l"(p));
    return a;
}
DINLINE bool elect_one() {
    uint32_t p;
    asm volatile("{ .reg .pred p; elect.sync _|p, 0xFFFFFFFF; selp.b32 %0, 1, 0, p; }" : "=r"(p));
    return p != 0;
}
DINLINE void cp_async16(uint32_t d, const void* s) {
    asm volatile("cp.async.cg.shared.global [%0], [%1], 16;" :: "r"(d), "l"(s));
}
DINLINE void cp_commit() { asm volatile("cp.async.commit_group;" ::: "memory"); }

DINLINE void ldmx4(uint32_t* r, uint32_t addr) {
    asm volatile("ldmatrix.sync.aligned.m8n8.x4.shared.b16 {%0,%1,%2,%3}, [%4];"
        : "=r"(r[0]), "=r"(r[1]), "=r"(r[2]), "=r"(r[3]) : "r"(addr));
}
DINLINE void mma16816(float* c, const uint32_t* a, uint32_t b0, uint32_t b1) {
    asm volatile("mma.sync.aligned.m16n8k16.row.col.f32.bf16.bf16.f32 "
        "{%0,%1,%2,%3}, {%4,%5,%6,%7}, {%8,%9}, {%0,%1,%2,%3};"
        : "+f"(c[0]), "+f"(c[1]), "+f"(c[2]), "+f"(c[3])
        : "r"(a[0]), "r"(a[1]), "r"(a[2]), "r"(a[3]), "r"(b0), "r"(b1));
}

#define MBARRIER_INIT(mbar_smem_addr, count) \
    asm volatile("mbarrier.init.shared.b64 [%0], %1;" \
        :: "r"((uint32_t)(mbar_smem_addr)), "r"((uint32_t)(count)) : "memory")

#define MBARRIER_WAIT_PARITY(mbar_smem_addr, phase_parity) do { \
    uint32_t _mbar = (uint32_t)(mbar_smem_addr); \
    uint32_t _parity = (uint32_t)(phase_parity); \
    uint32_t _done; \
    asm volatile( \
        "{\n\t" \
        ".reg .pred p;\n\t" \
        "mbarrier.try_wait.parity.acquire.cta.shared::cta.b64 p, [%1], %2;\n\t" \
        "selp.b32 %0, 1, 0, p;\n\t" \
        "}" \
        : "=r"(_done) : "r"(_mbar), "r"(_parity) : "memory"); \
    if (!_done) { \
        asm volatile( \
            "{\n\t" \
            ".reg .pred P1;\n\t" \
            "WAIT_LOOP_%=:\n\t" \
            "mbarrier.try_wait.parity.acquire.cta.shared::cta.b64 P1, [%0], %1, 0x989680;\n\t" \
            "@P1 bra.uni WAIT_DONE_%=;\n\t" \
            "bra.uni WAIT_LOOP_%=;\n\t" \
            "WAIT_DONE_%=:\n\t" \
            "}" \
            :: "r"(_mbar), "r"(_parity) : "memory"); \
    } \
} while(0)

// ---------------- tcgen05 helpers (only expanded when HAS_TCGEN05) ----------
#define TCGEN05_ALLOC(smem_result_addr, nCols) \
    asm volatile("tcgen05.alloc.cta_group::1.sync.aligned.shared::cta.b32 [%0], %1;" \
        :: "r"((uint32_t)(smem_result_addr)), "r"((uint32_t)(nCols)) : "memory")
#define TCGEN05_DEALLOC(tmem_addr, nCols) \
    asm volatile("tcgen05.dealloc.cta_group::1.sync.aligned.b32 %0, %1;" \
        :: "r"(tmem_addr), "r"(nCols))
#define TCGEN05_RELINQUISH_ALLOC_PERMIT() \
    asm volatile("tcgen05.relinquish_alloc_permit.cta_group::1.sync.aligned;")
#define TCGEN05_COMMIT(mbar_smem_addr) \
    asm volatile("tcgen05.commit.cta_group::1.mbarrier::arrive::one.shared::cluster.b64 [%0];" \
        :: "r"((uint32_t)(mbar_smem_addr)) : "memory")
#define TCGEN05_FENCE_BEFORE() asm volatile("tcgen05.fence::before_thread_sync;" ::: "memory")
#define TCGEN05_FENCE_AFTER()  asm volatile("tcgen05.fence::after_thread_sync;" ::: "memory")
#define TCGEN05_WAIT_LD()      asm volatile("tcgen05.wait::ld.sync.aligned;" ::: "memory")

#define TCGEN05_LD_32X32B_X32(r, tmem_addr) \
    asm volatile( \
        "tcgen05.ld.sync.aligned.32x32b.x32.b32 " \
        "{%0, %1, %2, %3, %4, %5, %6, %7, " \
        " %8, %9, %10, %11, %12, %13, %14, %15, " \
        " %16, %17, %18, %19, %20, %21, %22, %23, " \
        " %24, %25, %26, %27, %28, %29, %30, %31}, [%32];" \
        : "=r"((r)[0]),  "=r"((r)[1]),  "=r"((r)[2]),  "=r"((r)[3]), \
          "=r"((r)[4]),  "=r"((r)[5]),  "=r"((r)[6]),  "=r"((r)[7]), \
          "=r"((r)[8]),  "=r"((r)[9]),  "=r"((r)[10]), "=r"((r)[11]), \
          "=r"((r)[12]), "=r"((r)[13]), "=r"((r)[14]), "=r"((r)[15]), \
          "=r"((r)[16]), "=r"((r)[17]), "=r"((r)[18]), "=r"((r)[19]), \
          "=r"((r)[20]), "=r"((r)[21]), "=r"((r)[22]), "=r"((r)[23]), \
          "=r"((r)[24]), "=r"((r)[25]), "=r"((r)[26]), "=r"((r)[27]), \
          "=r"((r)[28]), "=r"((r)[29]), "=r"((r)[30]), "=r"((r)[31]) \
        : "r"(tmem_addr))

static constexpr uint64_t SMEM_DESC_BASE_SW128 =
    (uint64_t(2)  << 61) | (uint64_t(1) << 46) | (uint64_t(64) << 32) | (uint64_t(1) << 16);
#define MAKE_SMEM_DESC(base_addr) \
    (SMEM_DESC_BASE_SW128 | ((uint64_t)((base_addr) >> 4) & 0x3FFF))

#if HAS_TCGEN05
DINLINE void mma_f16_ss(uint32_t d, uint64_t ad, uint64_t bd, uint32_t idesc, uint32_t acc) {
    uint32_t z = 0;
    asm volatile(
        "{\n\t.reg .pred p;\n\tsetp.ne.u32 p, %5, 0;\n\t"
        "tcgen05.mma.cta_group::1.kind::f16 [%0], %1, %2, %3, {%4, %4, %4, %4}, p;\n\t}"
        :: "r"(d), "l"(ad), "l"(bd), "r"(idesc), "r"(z), "r"(acc)
        : "memory");
}
#endif

// ---------------- small kernels ----------------

// Detect whether categorical_features is int64 (odd 32-bit words all zero) or int32.
__global__ void detect_kernel(const unsigned int* __restrict__ w, int nwords) {
    __shared__ unsigned int red[256];
    unsigned int acc = 0;
    for (int i = 2 * threadIdx.x + 1; i < nwords; i += 512) acc |= w[i];
    red[threadIdx.x] = acc;
    __syncthreads();
    for (int s = 128; s > 0; s >>= 1) {
        if (threadIdx.x < (unsigned)s) red[threadIdx.x] |= red[threadIdx.x + s];
        __syncthreads();
    }
    if (threadIdx.x == 0) g_is64 = (red[0] == 0u) ? 1 : 0;
}

// Transpose+convert: in fp32 [K,N] row-major -> out bf16 [N,K] row-major.
__global__ void transpose_cvt(const float* __restrict__ in, __nv_bfloat16* __restrict__ out,
                              int K, int N) {
    __shared__ float tile[32][33];
    int nb = blockIdx.x * 32, kb = blockIdx.y * 32;
    #pragma unroll
    for (int i = threadIdx.y; i < 32; i += 8)
        tile[i][threadIdx.x] = in[(size_t)(kb + i) * N + nb + threadIdx.x];
    __syncthreads();
    #pragma unroll
    for (int i = threadIdx.y; i < 32; i += 8)
        out[(size_t)(nb + i) * K + kb + threadIdx.x] = __float2bfloat16(tile[threadIdx.x][i]);
}

// Dense bottom: H0[b, 0:128] = cont[b] @ W_cont + b_cont   (bf16)
__global__ void dense_kernel(const float* __restrict__ cont, const float* __restrict__ Wc,
                             const float* __restrict__ bc, __nv_bfloat16* __restrict__ H0) {
    __shared__ float sW[NCONT * EMB];
    __shared__ float sbv[EMB];
    for (int i = threadIdx.x; i < NCONT * EMB; i += 256) sW[i] = Wc[i];
    if (threadIdx.x < EMB) sbv[threadIdx.x] = bc[threadIdx.x];
    __syncthreads();
    int warp = threadIdx.x >> 5, lane = threadIdx.x & 31;
    int b = blockIdx.x * 8 + warp;
    float cf[NCONT];
    #pragma unroll
    for (int i = 0; i < NCONT; i++) cf[i] = __ldg(cont + (size_t)b * NCONT + i);
    uint32_t pk[2];
    #pragma unroll
    for (int h = 0; h < 2; h++) {
        float v[2];
        #pragma unroll
        for (int q = 0; q < 2; q++) {
            int col = lane * 4 + h * 2 + q;
            float a = sbv[col];
            #pragma unroll
            for (int i = 0; i < NCONT; i++) a = fmaf(cf[i], sW[i * EMB + col], a);
            v[q] = a;
        }
        asm("cvt.rn.bf16x2.f32 %0, %1, %2;" : "=r"(pk[h]) : "f"(v[1]), "f"(v[0]));
    }
    ((uint2*)(H0 + (size_t)b * K1))[lane] = make_uint2(pk[0], pk[1]);
}

// Embedding gather: one warp per (batch, table).
__global__ void gather_kernel(const void* __restrict__ cat, const float* __restrict__ tables,
                              __nv_bfloat16* __restrict__ H0) {
    int gw = (blockIdx.x * blockDim.x + threadIdx.x) >> 5;
    int lane = threadIdx.x & 31;
    if (gw >= BATCH * NTAB) return;
    int b = gw / NTAB, t = gw - b * NTAB;
    long long pos = (long long)b * NTAB + t;
    long long idx = g_is64 ? ((const long long*)cat)[pos]
                           : (long long)((const int*)cat)[pos];
    const float4* src = (const float4*)(tables + ((size_t)t * VOCAB + (size_t)idx) * EMB);
    float4 v = __ldg(src + lane);
    uint32_t lo, hi;
    asm("cvt.rn.bf16x2.f32 %0, %1, %2;" : "=r"(lo) : "f"(v.y), "f"(v.x));
    asm("cvt.rn.bf16x2.f32 %0, %1, %2;" : "=r"(hi) : "f"(v.w), "f"(v.z));
    ((uint2*)(H0 + (size_t)b * K1 + EMB + (size_t)t * EMB))[lane] = make_uint2(lo, hi);
}

// ---------------- GEMM: C = relu(A @ W^T + bias), bf16 in/out, f32 acc -------
// A: [Mtot, Ktot] bf16 row-major; Bw: [Ntot, Ktot] bf16 row-major.
#define STAGES       4
#define BM           128
#define BN           256
#define BK           64
#define GEMM_THREADS 256
#define STAGE_BYTES  ((BM + BN) * BK * 2)   /* 49152 (tcgen05 path) */
#define A_OFF        0
#define B_OFF        (BM * BK * 2)          /* 16384 */
#define SM_TMEM      0
#define SM_BARS      16
#define SM_TILES     1024
#define GEMM_SMEM    (SM_TILES + STAGES * STAGE_BYTES)  /* 197632 */
#define IDESC_F16    ((1u<<4)|(1u<<7)|(1u<<10)|((BN/8)<<17)|((BM/16)<<24))

// Fallback tiling: two sequential 128-wide N halves, 3-stage cp.async pipeline.
#define FB_STAGES      3
#define FB_STAGE_BYTES ((128 + 128) * BK * 2)   /* 32768 */
#define FB_B_OFF       (128 * BK * 2)           /* 16384 */

__global__ void __launch_bounds__(GEMM_THREADS, 1)
gemm_bf16_relu(const __nv_bfloat16* __restrict__ A,
               const __nv_bfloat16* __restrict__ Bw,
               const float* __restrict__ bias,
               __nv_bfloat16* __restrict__ C,
               int Ntot, int Ktot) {
#if HAS_TCGEN05
    // ================= tcgen05 path (sm_103a/f target) =================
    extern __shared__ __align__(1024) char smem[];
    const uint32_t sb = smem_u32(smem);
    const int tid = threadIdx.x, wid = tid >> 5, lane = tid & 31;
    const int ntn = Ntot / BN;
    const int mt = blockIdx.x / ntn, nt = blockIdx.x - mt * ntn;
    const int m0 = mt * BM, n0 = nt * BN;
    const int nch = Ktot / BK;

    if (wid == 0) TCGEN05_ALLOC(sb + SM_TMEM, 256);
    if (tid == 0) {
        #pragma unroll
        for (int s = 0; s < STAGES; s++) MBARRIER_INIT(sb + SM_BARS + 8 * s, 1);
        MBARRIER_INIT(sb + SM_BARS + 8 * STAGES, 1);
    }
    __syncthreads();
    uint32_t tmem;
    asm volatile("ld.shared.b32 %0, [%1];" : "=r"(tmem) : "r"(sb + SM_TMEM));

    const char* srcp[12];
    uint32_t   dsto[12];
    #pragma unroll
    for (int i = 0; i < 12; i++) {
        int g = tid + i * GEMM_THREADS;
        int r, c; uint32_t base; const __nv_bfloat16* gp;
        if (g < BM * 8) { r = g >> 3; c = g & 7; base = A_OFF; gp = A  + (size_t)(m0 + r) * Ktot; }
        else { int gb = g - BM * 8; r = gb >> 3; c = gb & 7; base = B_OFF; gp = Bw + (size_t)(n0 + r) * Ktot; }
        uint32_t boff = (uint32_t)r * 128u + (uint32_t)c * 16u;
        dsto[i] = base + (boff ^ ((boff >> 3) & 0x70u));
        srcp[i] = (const char*)gp + c * 16;
    }

    #pragma unroll
    for (int j = 0; j < STAGES - 1; j++) {
        uint32_t st = sb + SM_TILES + j * STAGE_BYTES;
        size_t ko = (size_t)j * (BK * 2);
        #pragma unroll
        for (int q = 0; q < 12; q++) cp_async16(st + dsto[q], srcp[q] + ko);
        cp_commit();
    }

    for (int i = 0; i < nch; i++) {
        int j = i + STAGES - 1;
        if (j < nch) {
            int sp = j & (STAGES - 1);
            if (j >= STAGES) {
                int ph = ((j >> 2) + 1) & 1;
                MBARRIER_WAIT_PARITY(sb + SM_BARS + 8 * sp, ph);
            }
            uint32_t st = sb + SM_TILES + sp * STAGE_BYTES;
            size_t ko = (size_t)j * (BK * 2);
            #pragma unroll
            for (int q = 0; q < 12; q++) cp_async16(st + dsto[q], srcp[q] + ko);
        }
        cp_commit();
        asm volatile("cp.async.wait_group 3;" ::: "memory");
        __syncthreads();
        if (wid == 0) {
            if (elect_one()) {
                asm volatile("fence.proxy.async.shared::cta;" ::: "memory");
                int sc = i & (STAGES - 1);
                uint32_t st = sb + SM_TILES + sc * STAGE_BYTES;
                uint64_t ad = MAKE_SMEM_DESC(st + A_OFF);
                uint64_t bd = MAKE_SMEM_DESC(st + B_OFF);
                #pragma unroll
                for (int k = 0; k < 4; k++)
                    mma_f16_ss(tmem, ad + 2 * k, bd + 2 * k, IDESC_F16,
                               (uint32_t)((i > 0) | (k > 0)));
                TCGEN05_COMMIT(sb + SM_BARS + 8 * sc);
            }
        }
    }
    if (wid == 0 && elect_one()) TCGEN05_COMMIT(sb + SM_BARS + 8 * STAGES);
    MBARRIER_WAIT_PARITY(sb + SM_BARS + 8 * STAGES, 0);
    TCGEN05_FENCE_AFTER();

    if (wid < 4) {
        int row = m0 + wid * 32 + lane;
        __nv_bfloat16* crow = C + (size_t)row * Ntot + n0;
        #pragma unroll
        for (int cb = 0; cb < BN; cb += 32) {
            uint32_t d[32];
            TCGEN05_LD_32X32B_X32(d, tmem + cb);
            TCGEN05_WAIT_LD();
            uint32_t pk[16];
            #pragma unroll
            for (int c = 0; c < 32; c += 2) {
                float v0 = fmaxf(__uint_as_float(d[c])     + __ldg(bias + n0 + cb + c),     0.f);
                float v1 = fmaxf(__uint_as_float(d[c + 1]) + __ldg(bias + n0 + cb + c + 1), 0.f);
                asm("cvt.rn.bf16x2.f32 %0, %1, %2;" : "=r"(pk[c >> 1]) : "f"(v1), "f"(v0));
            }
            TCGEN05_FENCE_BEFORE();
            uint4* dst = (uint4*)(crow + cb);
            #pragma unroll
            for (int q = 0; q < 4; q++) dst[q] = ((uint4*)pk)[q];
        }
    }
    __syncthreads();
    if (wid == 0) {
        TCGEN05_RELINQUISH_ALLOC_PERMIT();
        TCGEN05_DEALLOC(tmem, 256);
    }
#else
    // ================= mma.sync fallback (baseline sm_103) =================
    extern __shared__ __align__(1024) char smem[];
    const uint32_t sb = smem_u32(smem) + SM_TILES;   // tiles base
    const int tid = threadIdx.x, wid = tid >> 5, lane = tid & 31;
    const int ntn = Ntot / BN;
    const int mt = blockIdx.x / ntn, nt = blockIdx.x - mt * ntn;
    const int m0 = mt * BM, n0 = nt * BN;
    const int nch = Ktot / BK;
    const int wm = wid >> 1, wn = wid & 1;
    const int g4 = lane >> 2, tg = lane & 3;           // mma fragment coords
    const int lr = lane & 7, sel = lane >> 3;
    const int rowoff = ((sel & 1) << 3) + lr;          // ldmatrix row offset
    const int koff2  = (sel >> 1) << 4;                // ldmatrix k byte offset

    // Loader slots: 4 A granules + 4 B granules per thread (16B each).
    int rA[4], cA[4], rB[4], cB[4];
    const char* sAp[4];
    uint32_t dAo[4], dBo[4];
    #pragma unroll
    for (int q = 0; q < 4; q++) {
        int g = tid + q * 256;                 // 0..1023 -> A rows
        rA[q] = g >> 3; cA[q] = g & 7;
        rB[q] = g >> 3; cB[q] = g & 7;
        uint32_t ba = (uint32_t)rA[q] * 128u + (uint32_t)cA[q] * 16u;
        dAo[q] = (ba ^ ((ba >> 3) & 0x70u));
        uint32_t bb = (uint32_t)rB[q] * 128u + (uint32_t)cB[q] * 16u;
        dBo[q] = FB_B_OFF + (bb ^ ((bb >> 3) & 0x70u));
        sAp[q] = (const char*)(A + (size_t)(m0 + rA[q]) * Ktot) + cA[q] * 16;
    }

    // Per-lane ldmatrix address bases (h-independent).
    uint32_t aBase[2], aXor[2];
    #pragma unroll
    for (int mi = 0; mi < 2; mi++) {
        int row = wm * 32 + mi * 16 + rowoff;
        aBase[mi] = (uint32_t)row * 128u;
        aXor[mi]  = (uint32_t)(row & 7) << 4;
    }
    uint32_t bBase[4], bXor[4];
    #pragma unroll
    for (int ni = 0; ni < 4; ni++) {
        int row = wn * 64 + ni * 16 + rowoff;
        bBase[ni] = FB_B_OFF + (uint32_t)row * 128u;
        bXor[ni]  = (uint32_t)(row & 7) << 4;
    }

    for (int h = 0; h < 2; h++) {
        const char* sBp[4];
        #pragma unroll
        for (int q = 0; q < 4; q++)
            sBp[q] = (const char*)(Bw + (size_t)(n0 + h * 128 + rB[q]) * Ktot) + cB[q] * 16;

        float acc[2][8][4];
        #pragma unroll
        for (int mi = 0; mi < 2; mi++)
            #pragma unroll
            for (int j = 0; j < 8; j++)
                #pragma unroll
                for (int q = 0; q < 4; q++) acc[mi][j][q] = 0.f;

        // Prologue: stages 0..FB_STAGES-2
        #pragma unroll
        for (int s = 0; s < FB_STAGES - 1; s++) {
            uint32_t st = sb + s * FB_STAGE_BYTES;
            size_t ko = (size_t)s * (BK * 2);
            #pragma unroll
            for (int q = 0; q < 4; q++) cp_async16(st + dAo[q], sAp[q] + ko);
            #pragma unroll
            for (int q = 0; q < 4; q++) cp_async16(st + dBo[q], sBp[q] + ko);
            cp_commit();
        }

        for (int i = 0; i < nch; i++) {
            int j = i + FB_STAGES - 1;
            if (j < nch) {
                int sp = j % FB_STAGES;
                uint32_t st = sb + sp * FB_STAGE_BYTES;
                size_t ko = (size_t)j * (BK * 2);
                #pragma unroll
                for (int q = 0; q < 4; q++) cp_async16(st + dAo[q], sAp[q] + ko);
                #pragma unroll
                for (int q = 0; q < 4; q++) cp_async16(st + dBo[q], sBp[q] + ko);
            }
            cp_commit();
            asm volatile("cp.async.wait_group %0;" :: "n"(FB_STAGES - 1) : "memory");
            __syncthreads();

            uint32_t st = sb + (i % FB_STAGES) * FB_STAGE_BYTES;
            #pragma unroll
            for (int kk = 0; kk < 4; kk++) {           // 4 x k16 per BK=64 chunk
                uint32_t koffb = (uint32_t)(kk * 32) + koff2;
                uint32_t a[2][4];
                #pragma unroll
                for (int mi = 0; mi < 2; mi++)
                    ldmx4(a[mi], st + aBase[mi] + (koffb ^ aXor[mi]));
                #pragma unroll
                for (int ni = 0; ni < 4; ni++) {
                    uint32_t bb[4];
                    ldmx4(bb, st + bBase[ni] + (koffb ^ bXor[ni]));
                    #pragma unroll
                    for (int mi = 0; mi < 2; mi++) {
                        mma16816(acc[mi][2 * ni],     a[mi], bb[0], bb[2]);
                        mma16816(acc[mi][2 * ni + 1], a[mi], bb[1], bb[3]);
                    }
                }
            }
            __syncthreads();
        }

        // Epilogue: bias + relu + bf16 store.
        #pragma unroll
        for (int mi = 0; mi < 2; mi++) {
            int row = m0 + wm * 32 + mi * 16 + g4;
            #pragma unroll
            for (int j = 0; j < 8; j++) {
                int col = n0 + h * 128 + wn * 64 + j * 8 + tg * 2;
                float bz0 = __ldg(bias + col), bz1 = __ldg(bias + col + 1);
                float v0 = fmaxf(acc[mi][j][0] + bz0, 0.f);
                float v1 = fmaxf(acc[mi][j][1] + bz1, 0.f);
                float v2 = fmaxf(acc[mi][j][2] + bz0, 0.f);
                float v3 = fmaxf(acc[mi][j][3] + bz1, 0.f);
                uint32_t p0, p1;
                asm("cvt.rn.bf16x2.f32 %0, %1, %2;" : "=r"(p0) : "f"(v1), "f"(v0));
                asm("cvt.rn.bf16x2.f32 %0, %1, %2;" : "=r"(p1) : "f"(v3), "f"(v2));
                *(uint32_t*)(C + (size_t)row * Ntot + col)       = p0;
                *(uint32_t*)(C + (size_t)(row + 8) * Ntot + col) = p1;
            }
        }
        __syncthreads();
    }
#endif
}

// Final: out[b] = sigmoid(H3[b,:] @ W_out + b_out)
__global__ void final_kernel(const __nv_bfloat16* __restrict__ H3, const float* __restrict__ Wo,
                             const float* __restrict__ bo, float* __restrict__ out) {
    __shared__ float sW[N3];
    if (threadIdx.x < N3) sW[threadIdx.x] = Wo[threadIdx.x];
    __syncthreads();
    int warp = threadIdx.x >> 5, lane = threadIdx.x & 31;
    int b = blockIdx.x * 8 + warp;
    uint4 v = __ldg((const uint4*)(H3 + (size_t)b * N3) + lane);
    uint32_t u[4] = {v.x, v.y, v.z, v.w};
    float acc = 0.f;
    #pragma unroll
    for (int j = 0; j < 4; j++) {
        __nv_bfloat162 h2 = *reinterpret_cast<__nv_bfloat162*>(&u[j]);
        acc += __bfloat162float(h2.x) * sW[lane * 8 + 2 * j];
        acc += __bfloat162float(h2.y) * sW[lane * 8 + 2 * j + 1];
    }
    #pragma unroll
    for (int s = 16; s > 0; s >>= 1) acc += __shfl_xor_sync(0xffffffffu, acc, s);
    if (lane == 0) out[b] = 1.f / (1.f + expf(-(acc + bo[0])));
}

// ---------------- launcher ----------------
extern "C" void kernel_launch(void* const* d_in, const int* in_sizes, int n_in,
                              void* d_out, int out_size) {
    (void)in_sizes; (void)n_in; (void)out_size;
    const float* cont = (const float*)d_in[0];
    const void*  cat  = d_in[1];
    const float* emb  = (const float*)d_in[2];
    const float* Wc   = (const float*)d_in[3];
    const float* bc   = (const float*)d_in[4];
    const float* W1   = (const float*)d_in[5];
    const float* b1   = (const float*)d_in[6];
    const float* W2   = (const float*)d_in[7];
    const float* b2   = (const float*)d_in[8];
    const float* W3   = (const float*)d_in[9];
    const float* b3   = (const float*)d_in[10];
    const float* Wo   = (const float*)d_in[11];
    const float* bo   = (const float*)d_in[12];
    float* out = (float*)d_out;

    void *h0, *h1, *h2, *h3, *w1t, *w2t, *w3t;
    cudaGetSymbolAddress(&h0,  g_H0);
    cudaGetSymbolAddress(&h1,  g_H1);
    cudaGetSymbolAddress(&h2,  g_H2);
    cudaGetSymbolAddress(&h3,  g_H3);
    cudaGetSymbolAddress(&w1t, g_W1T);
    cudaGetSymbolAddress(&w2t, g_W2T);
    cudaGetSymbolAddress(&w3t, g_W3T);

    cudaFuncSetAttribute(gemm_bf16_relu,
                         cudaFuncAttributeMaxDynamicSharedMemorySize, GEMM_SMEM);

    detect_kernel<<<1, 256>>>((const unsigned int*)cat, BATCH * NTAB);

    transpose_cvt<<<dim3(N1 / 32, K1 / 32), dim3(32, 8)>>>(W1, (__nv_bfloat16*)w1t, K1, N1);
    transpose_cvt<<<dim3(N2 / 32, N1 / 32), dim3(32, 8)>>>(W2, (__nv_bfloat16*)w2t, N1, N2);
    transpose_cvt<<<dim3(N3 / 32, N2 / 32), dim3(32, 8)>>>(W3, (__nv_bfloat16*)w3t, N2, N3);

    dense_kernel<<<BATCH / 8, 256>>>(cont, Wc, bc, (__nv_bfloat16*)h0);
    gather_kernel<<<BATCH * NTAB / 8, 256>>>(cat, emb, (__nv_bfloat16*)h0);

    gemm_bf16_relu<<<(BATCH / BM) * (N1 / BN), GEMM_THREADS, GEMM_SMEM>>>(
        (const __nv_bfloat16*)h0, (const __nv_bfloat16*)w1t, b1, (__nv_bfloat16*)h1, N1, K1);
    gemm_bf16_relu<<<(BATCH / BM) * (N2 / BN), GEMM_THREADS, GEMM_SMEM>>>(
        (const __nv_bfloat16*)h1, (const __nv_bfloat16*)w2t, b2, (__nv_bfloat16*)h2, N2, N1);
    gemm_bf16_relu<<<(BATCH / BM) * (N3 / BN), GEMM_THREADS, GEMM_SMEM>>>(
        (const __nv_bfloat16*)h2, (const __nv_bfloat16*)w3t, b3, (__nv_bfloat16*)h3, N3, N2);

    final_kernel<<<BATCH / 8, 256>>>((const __nv_bfloat16*)h3, Wo, bo, out);
}

// round 6
// speedup vs baseline: 1.0043x; 1.0043x over previous
#include <cuda_runtime.h>
#include <cuda_bf16.h>
#include <cstdint>
#include <math.h>

#define DINLINE static __device__ __forceinline__

// Arch-feature detection: tcgen05 requires an 'a' (arch-specific) or 'f'
// (family-specific) compilation target. On plain sm_103 ptxas rejects it.
#if defined(__CUDA_ARCH_FEAT_SM103_ALL) || defined(__CUDA_ARCH_FEAT_SM100_ALL) || \
    defined(__CUDA_ARCH_SPECIFIC__) || defined(__CUDA_ARCH_FAMILY_SPECIFIC__)
#define HAS_TCGEN05 1
#else
#define HAS_TCGEN05 0
#endif

// ---------------- problem dims ----------------
#define BATCH   16384
#define NCONT   13
#define EMB     128
#define NTAB    26
#define VOCAB   100000
#define K1      3456      // EMB*(1+NTAB)
#define N1      1024
#define N2      512
#define N3      256

// ---------------- scratch (device globals; no allocs allowed) ----------------
__device__ __nv_bfloat16 g_H0[(size_t)BATCH * K1];
__device__ __nv_bfloat16 g_H1[(size_t)BATCH * N1];
__device__ __nv_bfloat16 g_H2[(size_t)BATCH * N2];
__device__ __nv_bfloat16 g_H3[(size_t)BATCH * N3];
__device__ __nv_bfloat16 g_W1T[(size_t)N1 * K1];
__device__ __nv_bfloat16 g_W2T[(size_t)N2 * N1];
__device__ __nv_bfloat16 g_W3T[(size_t)N3 * N2];
__device__ int g_is64;

// ---------------- baseline PTX helpers ----------------
DINLINE uint32_t smem_u32(const void* p) {
    uint32_t a;
    asm("{ .reg .u64 t; cvta.to.shared.u64 t, %1; cvt.u32.u64 %0, t; }" : "=r"(a) : "l"(p));
    return a;
}
DINLINE bool elect_one() {
    uint32_t p;
    asm volatile("{ .reg .pred p; elect.sync _|p, 0xFFFFFFFF; selp.b32 %0, 1, 0, p; }" : "=r"(p));
    return p != 0;
}
DINLINE void cp_async16(uint32_t d, const void* s) {
    asm volatile("cp.async.cg.shared.global [%0], [%1], 16;" :: "r"(d), "l"(s));
}
DINLINE void cp_commit() { asm volatile("cp.async.commit_group;" ::: "memory"); }

DINLINE void ldmx4(uint32_t* r, uint32_t addr) {
    asm volatile("ldmatrix.sync.aligned.m8n8.x4.shared.b16 {%0,%1,%2,%3}, [%4];"
        : "=r"(r[0]), "=r"(r[1]), "=r"(r[2]), "=r"(r[3]) : "r"(addr));
}
DINLINE void mma16816(float* c, const uint32_t* a, uint32_t b0, uint32_t b1) {
    asm volatile("mma.sync.aligned.m16n8k16.row.col.f32.bf16.bf16.f32 "
        "{%0,%1,%2,%3}, {%4,%5,%6,%7}, {%8,%9}, {%0,%1,%2,%3};"
        : "+f"(c[0]), "+f"(c[1]), "+f"(c[2]), "+f"(c[3])
        : "r"(a[0]), "r"(a[1]), "r"(a[2]), "r"(a[3]), "r"(b0), "r"(b1));
}

#define MBARRIER_INIT(mbar_smem_addr, count) \
    asm volatile("mbarrier.init.shared.b64 [%0], %1;" \
        :: "r"((uint32_t)(mbar_smem_addr)), "r"((uint32_t)(count)) : "memory")

#define MBARRIER_WAIT_PARITY(mbar_smem_addr, phase_parity) do { \
    uint32_t _mbar = (uint32_t)(mbar_smem_addr); \
    uint32_t _parity = (uint32_t)(phase_parity); \
    uint32_t _done; \
    asm volatile( \
        "{\n\t" \
        ".reg .pred p;\n\t" \
        "mbarrier.try_wait.parity.acquire.cta.shared::cta.b64 p, [%1], %2;\n\t" \
        "selp.b32 %0, 1, 0, p;\n\t" \
        "}" \
        : "=r"(_done) : "r"(_mbar), "r"(_parity) : "memory"); \
    if (!_done) { \
        asm volatile( \
            "{\n\t" \
            ".reg .pred P1;\n\t" \
            "WAIT_LOOP_%=:\n\t" \
            "mbarrier.try_wait.parity.acquire.cta.shared::cta.b64 P1, [%0], %1, 0x989680;\n\t" \
            "@P1 bra.uni WAIT_DONE_%=;\n\t" \
            "bra.uni WAIT_LOOP_%=;\n\t" \
            "WAIT_DONE_%=:\n\t" \
            "}" \
            :: "r"(_mbar), "r"(_parity) : "memory"); \
    } \
} while(0)

// ---------------- tcgen05 helpers (only expanded when HAS_TCGEN05) ----------
#define TCGEN05_ALLOC(smem_result_addr, nCols) \
    asm volatile("tcgen05.alloc.cta_group::1.sync.aligned.shared::cta.b32 [%0], %1;" \
        :: "r"((uint32_t)(smem_result_addr)), "r"((uint32_t)(nCols)) : "memory")
#define TCGEN05_DEALLOC(tmem_addr, nCols) \
    asm volatile("tcgen05.dealloc.cta_group::1.sync.aligned.b32 %0, %1;" \
        :: "r"(tmem_addr), "r"(nCols))
#define TCGEN05_RELINQUISH_ALLOC_PERMIT() \
    asm volatile("tcgen05.relinquish_alloc_permit.cta_group::1.sync.aligned;")
#define TCGEN05_COMMIT(mbar_smem_addr) \
    asm volatile("tcgen05.commit.cta_group::1.mbarrier::arrive::one.shared::cluster.b64 [%0];" \
        :: "r"((uint32_t)(mbar_smem_addr)) : "memory")
#define TCGEN05_FENCE_BEFORE() asm volatile("tcgen05.fence::before_thread_sync;" ::: "memory")
#define TCGEN05_FENCE_AFTER()  asm volatile("tcgen05.fence::after_thread_sync;" ::: "memory")
#define TCGEN05_WAIT_LD()      asm volatile("tcgen05.wait::ld.sync.aligned;" ::: "memory")

#define TCGEN05_LD_32X32B_X32(r, tmem_addr) \
    asm volatile( \
        "tcgen05.ld.sync.aligned.32x32b.x32.b32 " \
        "{%0, %1, %2, %3, %4, %5, %6, %7, " \
        " %8, %9, %10, %11, %12, %13, %14, %15, " \
        " %16, %17, %18, %19, %20, %21, %22, %23, " \
        " %24, %25, %26, %27, %28, %29, %30, %31}, [%32];" \
        : "=r"((r)[0]),  "=r"((r)[1]),  "=r"((r)[2]),  "=r"((r)[3]), \
          "=r"((r)[4]),  "=r"((r)[5]),  "=r"((r)[6]),  "=r"((r)[7]), \
          "=r"((r)[8]),  "=r"((r)[9]),  "=r"((r)[10]), "=r"((r)[11]), \
          "=r"((r)[12]), "=r"((r)[13]), "=r"((r)[14]), "=r"((r)[15]), \
          "=r"((r)[16]), "=r"((r)[17]), "=r"((r)[18]), "=r"((r)[19]), \
          "=r"((r)[20]), "=r"((r)[21]), "=r"((r)[22]), "=r"((r)[23]), \
          "=r"((r)[24]), "=r"((r)[25]), "=r"((r)[26]), "=r"((r)[27]), \
          "=r"((r)[28]), "=r"((r)[29]), "=r"((r)[30]), "=r"((r)[31]) \
        : "r"(tmem_addr))

static constexpr uint64_t SMEM_DESC_BASE_SW128 =
    (uint64_t(2)  << 61) | (uint64_t(1) << 46) | (uint64_t(64) << 32) | (uint64_t(1) << 16);
#define MAKE_SMEM_DESC(base_addr) \
    (SMEM_DESC_BASE_SW128 | ((uint64_t)((base_addr) >> 4) & 0x3FFF))

#if HAS_TCGEN05
DINLINE void mma_f16_ss(uint32_t d, uint64_t ad, uint64_t bd, uint32_t idesc, uint32_t acc) {
    uint32_t z = 0;
    asm volatile(
        "{\n\t.reg .pred p;\n\tsetp.ne.u32 p, %5, 0;\n\t"
        "tcgen05.mma.cta_group::1.kind::f16 [%0], %1, %2, %3, {%4, %4, %4, %4}, p;\n\t}"
        :: "r"(d), "l"(ad), "l"(bd), "r"(idesc), "r"(z), "r"(acc)
        : "memory");
}
#endif

// ---------------- small kernels ----------------

// Detect whether categorical_features is int64 (odd 32-bit words all zero) or int32.
__global__ void detect_kernel(const unsigned int* __restrict__ w, int nwords) {
    __shared__ unsigned int red[256];
    unsigned int acc = 0;
    for (int i = 2 * threadIdx.x + 1; i < nwords; i += 512) acc |= w[i];
    red[threadIdx.x] = acc;
    __syncthreads();
    for (int s = 128; s > 0; s >>= 1) {
        if (threadIdx.x < (unsigned)s) red[threadIdx.x] |= red[threadIdx.x + s];
        __syncthreads();
    }
    if (threadIdx.x == 0) g_is64 = (red[0] == 0u) ? 1 : 0;
}

// Transpose+convert: in fp32 [K,N] row-major -> out bf16 [N,K] row-major.
__global__ void transpose_cvt(const float* __restrict__ in, __nv_bfloat16* __restrict__ out,
                              int K, int N) {
    __shared__ float tile[32][33];
    int nb = blockIdx.x * 32, kb = blockIdx.y * 32;
    #pragma unroll
    for (int i = threadIdx.y; i < 32; i += 8)
        tile[i][threadIdx.x] = in[(size_t)(kb + i) * N + nb + threadIdx.x];
    __syncthreads();
    #pragma unroll
    for (int i = threadIdx.y; i < 32; i += 8)
        out[(size_t)(nb + i) * K + kb + threadIdx.x] = __float2bfloat16(tile[threadIdx.x][i]);
}

// Dense bottom: H0[b, 0:128] = cont[b] @ W_cont + b_cont   (bf16)
__global__ void dense_kernel(const float* __restrict__ cont, const float* __restrict__ Wc,
                             const float* __restrict__ bc, __nv_bfloat16* __restrict__ H0) {
    __shared__ float sW[NCONT * EMB];
    __shared__ float sbv[EMB];
    for (int i = threadIdx.x; i < NCONT * EMB; i += 256) sW[i] = Wc[i];
    if (threadIdx.x < EMB) sbv[threadIdx.x] = bc[threadIdx.x];
    __syncthreads();
    int warp = threadIdx.x >> 5, lane = threadIdx.x & 31;
    int b = blockIdx.x * 8 + warp;
    float cf[NCONT];
    #pragma unroll
    for (int i = 0; i < NCONT; i++) cf[i] = __ldg(cont + (size_t)b * NCONT + i);
    uint32_t pk[2];
    #pragma unroll
    for (int h = 0; h < 2; h++) {
        float v[2];
        #pragma unroll
        for (int q = 0; q < 2; q++) {
            int col = lane * 4 + h * 2 + q;
            float a = sbv[col];
            #pragma unroll
            for (int i = 0; i < NCONT; i++) a = fmaf(cf[i], sW[i * EMB + col], a);
            v[q] = a;
        }
        asm("cvt.rn.bf16x2.f32 %0, %1, %2;" : "=r"(pk[h]) : "f"(v[1]), "f"(v[0]));
    }
    ((uint2*)(H0 + (size_t)b * K1))[lane] = make_uint2(pk[0], pk[1]);
}

// Embedding gather: one warp per (batch, table).
__global__ void gather_kernel(const void* __restrict__ cat, const float* __restrict__ tables,
                              __nv_bfloat16* __restrict__ H0) {
    int gw = (blockIdx.x * blockDim.x + threadIdx.x) >> 5;
    int lane = threadIdx.x & 31;
    if (gw >= BATCH * NTAB) return;
    int b = gw / NTAB, t = gw - b * NTAB;
    long long pos = (long long)b * NTAB + t;
    long long idx = g_is64 ? ((const long long*)cat)[pos]
                           : (long long)((const int*)cat)[pos];
    const float4* src = (const float4*)(tables + ((size_t)t * VOCAB + (size_t)idx) * EMB);
    float4 v = __ldg(src + lane);
    uint32_t lo, hi;
    asm("cvt.rn.bf16x2.f32 %0, %1, %2;" : "=r"(lo) : "f"(v.y), "f"(v.x));
    asm("cvt.rn.bf16x2.f32 %0, %1, %2;" : "=r"(hi) : "f"(v.w), "f"(v.z));
    ((uint2*)(H0 + (size_t)b * K1 + EMB + (size_t)t * EMB))[lane] = make_uint2(lo, hi);
}

// ---------------- GEMM: C = relu(A @ W^T + bias), bf16 in/out, f32 acc -------
// A: [Mtot, Ktot] bf16 row-major; Bw: [Ntot, Ktot] bf16 row-major.
#define STAGES       4
#define BM           128
#define BN           256
#define BK           64
#define GEMM_THREADS 256
#define STAGE_BYTES  ((BM + BN) * BK * 2)   /* 49152 (tcgen05 path) */
#define A_OFF        0
#define B_OFF        (BM * BK * 2)          /* 16384 */
#define SM_TMEM      0
#define SM_BARS      16
#define SM_TILES     1024
#define GEMM_SMEM    (SM_TILES + STAGES * STAGE_BYTES)  /* 197632 */
#define IDESC_F16    ((1u<<4)|(1u<<7)|(1u<<10)|((BN/8)<<17)|((BM/16)<<24))

// Fallback tiling: two sequential 128-wide N halves, 3-stage cp.async pipeline.
#define FB_STAGES      3
#define FB_STAGE_BYTES ((128 + 128) * BK * 2)   /* 32768 */
#define FB_B_OFF       (128 * BK * 2)           /* 16384 */

__global__ void __launch_bounds__(GEMM_THREADS, 1)
gemm_bf16_relu(const __nv_bfloat16* __restrict__ A,
               const __nv_bfloat16* __restrict__ Bw,
               const float* __restrict__ bias,
               __nv_bfloat16* __restrict__ C,
               int Ntot, int Ktot) {
#if HAS_TCGEN05
    // ================= tcgen05 path (sm_103a/f target) =================
    extern __shared__ __align__(1024) char smem[];
    const uint32_t sb = smem_u32(smem);
    const int tid = threadIdx.x, wid = tid >> 5, lane = tid & 31;
    const int ntn = Ntot / BN;
    const int mt = blockIdx.x / ntn, nt = blockIdx.x - mt * ntn;
    const int m0 = mt * BM, n0 = nt * BN;
    const int nch = Ktot / BK;

    if (wid == 0) TCGEN05_ALLOC(sb + SM_TMEM, 256);
    if (tid == 0) {
        #pragma unroll
        for (int s = 0; s < STAGES; s++) MBARRIER_INIT(sb + SM_BARS + 8 * s, 1);
        MBARRIER_INIT(sb + SM_BARS + 8 * STAGES, 1);
    }
    __syncthreads();
    uint32_t tmem;
    asm volatile("ld.shared.b32 %0, [%1];" : "=r"(tmem) : "r"(sb + SM_TMEM));

    const char* srcp[12];
    uint32_t   dsto[12];
    #pragma unroll
    for (int i = 0; i < 12; i++) {
        int g = tid + i * GEMM_THREADS;
        int r, c; uint32_t base; const __nv_bfloat16* gp;
        if (g < BM * 8) { r = g >> 3; c = g & 7; base = A_OFF; gp = A  + (size_t)(m0 + r) * Ktot; }
        else { int gb = g - BM * 8; r = gb >> 3; c = gb & 7; base = B_OFF; gp = Bw + (size_t)(n0 + r) * Ktot; }
        uint32_t boff = (uint32_t)r * 128u + (uint32_t)c * 16u;
        dsto[i] = base + (boff ^ ((boff >> 3) & 0x70u));
        srcp[i] = (const char*)gp + c * 16;
    }

    #pragma unroll
    for (int j = 0; j < STAGES - 1; j++) {
        uint32_t st = sb + SM_TILES + j * STAGE_BYTES;
        size_t ko = (size_t)j * (BK * 2);
        #pragma unroll
        for (int q = 0; q < 12; q++) cp_async16(st + dsto[q], srcp[q] + ko);
        cp_commit();
    }

    for (int i = 0; i < nch; i++) {
        int j = i + STAGES - 1;
        if (j < nch) {
            int sp = j & (STAGES - 1);
            if (j >= STAGES) {
                int ph = ((j >> 2) + 1) & 1;
                MBARRIER_WAIT_PARITY(sb + SM_BARS + 8 * sp, ph);
            }
            uint32_t st = sb + SM_TILES + sp * STAGE_BYTES;
            size_t ko = (size_t)j * (BK * 2);
            #pragma unroll
            for (int q = 0; q < 12; q++) cp_async16(st + dsto[q], srcp[q] + ko);
        }
        cp_commit();
        asm volatile("cp.async.wait_group 3;" ::: "memory");
        __syncthreads();
        if (wid == 0) {
            if (elect_one()) {
                asm volatile("fence.proxy.async.shared::cta;" ::: "memory");
                int sc = i & (STAGES - 1);
                uint32_t st = sb + SM_TILES + sc * STAGE_BYTES;
                uint64_t ad = MAKE_SMEM_DESC(st + A_OFF);
                uint64_t bd = MAKE_SMEM_DESC(st + B_OFF);
                #pragma unroll
                for (int k = 0; k < 4; k++)
                    mma_f16_ss(tmem, ad + 2 * k, bd + 2 * k, IDESC_F16,
                               (uint32_t)((i > 0) | (k > 0)));
                TCGEN05_COMMIT(sb + SM_BARS + 8 * sc);
            }
        }
    }
    if (wid == 0 && elect_one()) TCGEN05_COMMIT(sb + SM_BARS + 8 * STAGES);
    MBARRIER_WAIT_PARITY(sb + SM_BARS + 8 * STAGES, 0);
    TCGEN05_FENCE_AFTER();

    if (wid < 4) {
        int row = m0 + wid * 32 + lane;
        __nv_bfloat16* crow = C + (size_t)row * Ntot + n0;
        #pragma unroll
        for (int cb = 0; cb < BN; cb += 32) {
            uint32_t d[32];
            TCGEN05_LD_32X32B_X32(d, tmem + cb);
            TCGEN05_WAIT_LD();
            uint32_t pk[16];
            #pragma unroll
            for (int c = 0; c < 32; c += 2) {
                float v0 = fmaxf(__uint_as_float(d[c])     + __ldg(bias + n0 + cb + c),     0.f);
                float v1 = fmaxf(__uint_as_float(d[c + 1]) + __ldg(bias + n0 + cb + c + 1), 0.f);
                asm("cvt.rn.bf16x2.f32 %0, %1, %2;" : "=r"(pk[c >> 1]) : "f"(v1), "f"(v0));
            }
            TCGEN05_FENCE_BEFORE();
            uint4* dst = (uint4*)(crow + cb);
            #pragma unroll
            for (int q = 0; q < 4; q++) dst[q] = ((uint4*)pk)[q];
        }
    }
    __syncthreads();
    if (wid == 0) {
        TCGEN05_RELINQUISH_ALLOC_PERMIT();
        TCGEN05_DEALLOC(tmem, 256);
    }
#else
    // ================= mma.sync fallback (baseline sm_103) =================
    extern __shared__ __align__(1024) char smem[];
    const uint32_t sb = smem_u32(smem) + SM_TILES;   // tiles base
    const int tid = threadIdx.x, wid = tid >> 5, lane = tid & 31;
    const int ntn = Ntot / BN;
    const int mt = blockIdx.x / ntn, nt = blockIdx.x - mt * ntn;
    const int m0 = mt * BM, n0 = nt * BN;
    const int nch = Ktot / BK;
    const int wm = wid >> 1, wn = wid & 1;
    const int g4 = lane >> 2, tg = lane & 3;           // mma fragment coords
    const int lr = lane & 7, sel = lane >> 3;
    const int rowoff = ((sel & 1) << 3) + lr;          // ldmatrix row offset
    const int koff2  = (sel >> 1) << 4;                // ldmatrix k byte offset

    // Loader slots: 4 A granules + 4 B granules per thread (16B each).
    int rA[4], cA[4], rB[4], cB[4];
    const char* sAp[4];
    uint32_t dAo[4], dBo[4];
    #pragma unroll
    for (int q = 0; q < 4; q++) {
        int g = tid + q * 256;                 // 0..1023 -> A rows
        rA[q] = g >> 3; cA[q] = g & 7;
        rB[q] = g >> 3; cB[q] = g & 7;
        uint32_t ba = (uint32_t)rA[q] * 128u + (uint32_t)cA[q] * 16u;
        dAo[q] = (ba ^ ((ba >> 3) & 0x70u));
        uint32_t bb = (uint32_t)rB[q] * 128u + (uint32_t)cB[q] * 16u;
        dBo[q] = FB_B_OFF + (bb ^ ((bb >> 3) & 0x70u));
        sAp[q] = (const char*)(A + (size_t)(m0 + rA[q]) * Ktot) + cA[q] * 16;
    }

    // Per-lane ldmatrix address bases (h-independent).
    uint32_t aBase[2], aXor[2];
    #pragma unroll
    for (int mi = 0; mi < 2; mi++) {
        int row = wm * 32 + mi * 16 + rowoff;
        aBase[mi] = (uint32_t)row * 128u;
        aXor[mi]  = (uint32_t)(row & 7) << 4;
    }
    uint32_t bBase[4], bXor[4];
    #pragma unroll
    for (int ni = 0; ni < 4; ni++) {
        int row = wn * 64 + ni * 16 + rowoff;
        bBase[ni] = FB_B_OFF + (uint32_t)row * 128u;
        bXor[ni]  = (uint32_t)(row & 7) << 4;
    }

    for (int h = 0; h < 2; h++) {
        const char* sBp[4];
        #pragma unroll
        for (int q = 0; q < 4; q++)
            sBp[q] = (const char*)(Bw + (size_t)(n0 + h * 128 + rB[q]) * Ktot) + cB[q] * 16;

        float acc[2][8][4];
        #pragma unroll
        for (int mi = 0; mi < 2; mi++)
            #pragma unroll
            for (int j = 0; j < 8; j++)
                #pragma unroll
                for (int q = 0; q < 4; q++) acc[mi][j][q] = 0.f;

        // Prologue: stages 0..FB_STAGES-2
        #pragma unroll
        for (int s = 0; s < FB_STAGES - 1; s++) {
            uint32_t st = sb + s * FB_STAGE_BYTES;
            size_t ko = (size_t)s * (BK * 2);
            #pragma unroll
            for (int q = 0; q < 4; q++) cp_async16(st + dAo[q], sAp[q] + ko);
            #pragma unroll
            for (int q = 0; q < 4; q++) cp_async16(st + dBo[q], sBp[q] + ko);
            cp_commit();
        }

        for (int i = 0; i < nch; i++) {
            int j = i + FB_STAGES - 1;
            if (j < nch) {
                int sp = j % FB_STAGES;
                uint32_t st = sb + sp * FB_STAGE_BYTES;
                size_t ko = (size_t)j * (BK * 2);
                #pragma unroll
                for (int q = 0; q < 4; q++) cp_async16(st + dAo[q], sAp[q] + ko);
                #pragma unroll
                for (int q = 0; q < 4; q++) cp_async16(st + dBo[q], sBp[q] + ko);
            }
            cp_commit();
            asm volatile("cp.async.wait_group %0;" :: "n"(FB_STAGES - 1) : "memory");
            __syncthreads();

            uint32_t st = sb + (i % FB_STAGES) * FB_STAGE_BYTES;
            #pragma unroll
            for (int kk = 0; kk < 4; kk++) {           // 4 x k16 per BK=64 chunk
                uint32_t koffb = (uint32_t)(kk * 32) + koff2;
                uint32_t a[2][4];
                #pragma unroll
                for (int mi = 0; mi < 2; mi++)
                    ldmx4(a[mi], st + aBase[mi] + (koffb ^ aXor[mi]));
                #pragma unroll
                for (int ni = 0; ni < 4; ni++) {
                    uint32_t bb[4];
                    ldmx4(bb, st + bBase[ni] + (koffb ^ bXor[ni]));
                    #pragma unroll
                    for (int mi = 0; mi < 2; mi++) {
                        mma16816(acc[mi][2 * ni],     a[mi], bb[0], bb[2]);
                        mma16816(acc[mi][2 * ni + 1], a[mi], bb[1], bb[3]);
                    }
                }
            }
            __syncthreads();
        }

        // Epilogue: bias + relu + bf16 store.
        #pragma unroll
        for (int mi = 0; mi < 2; mi++) {
            int row = m0 + wm * 32 + mi * 16 + g4;
            #pragma unroll
            for (int j = 0; j < 8; j++) {
                int col = n0 + h * 128 + wn * 64 + j * 8 + tg * 2;
                float bz0 = __ldg(bias + col), bz1 = __ldg(bias + col + 1);
                float v0 = fmaxf(acc[mi][j][0] + bz0, 0.f);
                float v1 = fmaxf(acc[mi][j][1] + bz1, 0.f);
                float v2 = fmaxf(acc[mi][j][2] + bz0, 0.f);
                float v3 = fmaxf(acc[mi][j][3] + bz1, 0.f);
                uint32_t p0, p1;
                asm("cvt.rn.bf16x2.f32 %0, %1, %2;" : "=r"(p0) : "f"(v1), "f"(v0));
                asm("cvt.rn.bf16x2.f32 %0, %1, %2;" : "=r"(p1) : "f"(v3), "f"(v2));
                *(uint32_t*)(C + (size_t)row * Ntot + col)       = p0;
                *(uint32_t*)(C + (size_t)(row + 8) * Ntot + col) = p1;
            }
        }
        __syncthreads();
    }
#endif
}

// Final: out[b] = sigmoid(H3[b,:] @ W_out + b_out)
__global__ void final_kernel(const __nv_bfloat16* __restrict__ H3, const float* __restrict__ Wo,
                             const float* __restrict__ bo, float* __restrict__ out) {
    __shared__ float sW[N3];
    if (threadIdx.x < N3) sW[threadIdx.x] = Wo[threadIdx.x];
    __syncthreads();
    int warp = threadIdx.x >> 5, lane = threadIdx.x & 31;
    int b = blockIdx.x * 8 + warp;
    uint4 v = __ldg((const uint4*)(H3 + (size_t)b * N3) + lane);
    uint32_t u[4] = {v.x, v.y, v.z, v.w};
    float acc = 0.f;
    #pragma unroll
    for (int j = 0; j < 4; j++) {
        __nv_bfloat162 h2 = *reinterpret_cast<__nv_bfloat162*>(&u[j]);
        acc += __bfloat162float(h2.x) * sW[lane * 8 + 2 * j];
        acc += __bfloat162float(h2.y) * sW[lane * 8 + 2 * j + 1];
    }
    #pragma unroll
    for (int s = 16; s > 0; s >>= 1) acc += __shfl_xor_sync(0xffffffffu, acc, s);
    if (lane == 0) out[b] = 1.f / (1.f + expf(-(acc + bo[0])));
}

// ---------------- launcher ----------------
extern "C" void kernel_launch(void* const* d_in, const int* in_sizes, int n_in,
                              void* d_out, int out_size) {
    (void)in_sizes; (void)n_in; (void)out_size;
    const float* cont = (const float*)d_in[0];
    const void*  cat  = d_in[1];
    const float* emb  = (const float*)d_in[2];
    const float* Wc   = (const float*)d_in[3];
    const float* bc   = (const float*)d_in[4];
    const float* W1   = (const float*)d_in[5];
    const float* b1   = (const float*)d_in[6];
    const float* W2   = (const float*)d_in[7];
    const float* b2   = (const float*)d_in[8];
    const float* W3   = (const float*)d_in[9];
    const float* b3   = (const float*)d_in[10];
    const float* Wo   = (const float*)d_in[11];
    const float* bo   = (const float*)d_in[12];
    float* out = (float*)d_out;

    void *h0, *h1, *h2, *h3, *w1t, *w2t, *w3t;
    cudaGetSymbolAddress(&h0,  g_H0);
    cudaGetSymbolAddress(&h1,  g_H1);
    cudaGetSymbolAddress(&h2,  g_H2);
    cudaGetSymbolAddress(&h3,  g_H3);
    cudaGetSymbolAddress(&w1t, g_W1T);
    cudaGetSymbolAddress(&w2t, g_W2T);
    cudaGetSymbolAddress(&w3t, g_W3T);

    cudaFuncSetAttribute(gemm_bf16_relu,
                         cudaFuncAttributeMaxDynamicSharedMemorySize, GEMM_SMEM);

    detect_kernel<<<1, 256>>>((const unsigned int*)cat, BATCH * NTAB);

    transpose_cvt<<<dim3(N1 / 32, K1 / 32), dim3(32, 8)>>>(W1, (__nv_bfloat16*)w1t, K1, N1);
    transpose_cvt<<<dim3(N2 / 32, N1 / 32), dim3(32, 8)>>>(W2, (__nv_bfloat16*)w2t, N1, N2);
    transpose_cvt<<<dim3(N3 / 32, N2 / 32), dim3(32, 8)>>>(W3, (__nv_bfloat16*)w3t, N2, N3);

    dense_kernel<<<BATCH / 8, 256>>>(cont, Wc, bc, (__nv_bfloat16*)h0);
    gather_kernel<<<BATCH * NTAB / 8, 256>>>(cat, emb, (__nv_bfloat16*)h0);

    gemm_bf16_relu<<<(BATCH / BM) * (N1 / BN), GEMM_THREADS, GEMM_SMEM>>>(
        (const __nv_bfloat16*)h0, (const __nv_bfloat16*)w1t, b1, (__nv_bfloat16*)h1, N1, K1);
    gemm_bf16_relu<<<(BATCH / BM) * (N2 / BN), GEMM_THREADS, GEMM_SMEM>>>(
        (const __nv_bfloat16*)h1, (const __nv_bfloat16*)w2t, b2, (__nv_bfloat16*)h2, N2, N1);
    gemm_bf16_relu<<<(BATCH / BM) * (N3 / BN), GEMM_THREADS, GEMM_SMEM>>>(
        (const __nv_bfloat16*)h2, (const __nv_bfloat16*)w3t, b3, (__nv_bfloat16*)h3, N3, N2);

    final_kernel<<<BATCH / 8, 256>>>((const __nv_bfloat16*)h3, Wo, bo, out);
}